// round 14
// baseline (speedup 1.0000x reference)
#include <cuda_runtime.h>
#include <cstdint>
#include <cstddef>

// BertBiLstmCrf: BiLSTM(768->2x384) -> FC(768->12) -> Viterbi
// B=64, T=512, H=768, LH=384, L=12. Output: [score(64); path(64*512)] f32.
// All-fp32 FFMA implementation (tensor paths unavailable/slow on this target).

#define NEGV (-1000.0f)

__device__ float        g_pre[(size_t)32768 * 3072];   // [t*64+b][dir*1536+row]
__device__ float        g_h[2][512][384][64];          // [dir][t][k][b]
__device__ float        g_feat[512][64][12];
__device__ unsigned char g_ptr[511][64][12];
__device__ unsigned int g_bar[8];

__global__ void k_init() { if (threadIdx.x < 8) g_bar[threadIdx.x] = 0u; }

// ---------------------------------------------------------------------------
// Kernel 1: input-projection SGEMM (unchanged from R13 best).
// 128x128 tile, BK=8, 256 threads, 8x8 per thread, global prefetch, 2 CTA/SM.
// ---------------------------------------------------------------------------
__global__ __launch_bounds__(256, 2) void k_gemm(
    const float* __restrict__ hs,
    const float* __restrict__ wf, const float* __restrict__ wb,
    const float* __restrict__ bif, const float* __restrict__ bhf,
    const float* __restrict__ bib, const float* __restrict__ bhb)
{
    __shared__ float As[8][128];
    __shared__ float Bs[8][128];
    const int tid = threadIdx.x;
    const int m0 = blockIdx.y * 128;
    const int n0 = blockIdx.x * 128;

    const int lr = tid >> 1;           // tile row 0..127
    const int lk = (tid & 1) * 4;      // k offset 0 or 4
    const int m  = m0 + lr;
    const float* arow = hs + ((size_t)(m & 63) * 512 + (m >> 6)) * 768 + lk;
    const int nrow = n0 + lr;
    const float* brow = (nrow < 1536) ? (wf + (size_t)nrow * 768 + lk)
                                      : (wb + (size_t)(nrow - 1536) * 768 + lk);

    const int ty = tid >> 4, tx = tid & 15;

    float acc[8][8];
#pragma unroll
    for (int i = 0; i < 8; i++)
#pragma unroll
        for (int j = 0; j < 8; j++) acc[i][j] = 0.f;

    float4 a4 = *(const float4*)(arow);
    float4 b4 = *(const float4*)(brow);

    for (int k0 = 0; k0 < 768; k0 += 8) {
        As[lk+0][lr] = a4.x; As[lk+1][lr] = a4.y; As[lk+2][lr] = a4.z; As[lk+3][lr] = a4.w;
        Bs[lk+0][lr] = b4.x; Bs[lk+1][lr] = b4.y; Bs[lk+2][lr] = b4.z; Bs[lk+3][lr] = b4.w;
        __syncthreads();
        if (k0 + 8 < 768) {
            a4 = *(const float4*)(arow + k0 + 8);
            b4 = *(const float4*)(brow + k0 + 8);
        }
#pragma unroll
        for (int kk = 0; kk < 8; kk++) {
            float af[8], bf[8];
            *(float4*)(af)     = *(const float4*)&As[kk][ty*8];
            *(float4*)(af + 4) = *(const float4*)&As[kk][ty*8 + 4];
            *(float4*)(bf)     = *(const float4*)&Bs[kk][tx*8];
            *(float4*)(bf + 4) = *(const float4*)&Bs[kk][tx*8 + 4];
#pragma unroll
            for (int i = 0; i < 8; i++)
#pragma unroll
                for (int j = 0; j < 8; j++)
                    acc[i][j] = fmaf(af[i], bf[j], acc[i][j]);
        }
        __syncthreads();
    }

    float bias[8];
#pragma unroll
    for (int j = 0; j < 8; j++) {
        int n = n0 + tx*8 + j;
        bias[j] = (n < 1536) ? (bif[n] + bhf[n]) : (bib[n - 1536] + bhb[n - 1536]);
    }
#pragma unroll
    for (int i = 0; i < 8; i++) {
        size_t row = (size_t)(m0 + ty*8 + i) * 3072 + (size_t)(n0 + tx*8);
        float4 v0, v1;
        v0.x = acc[i][0] + bias[0]; v0.y = acc[i][1] + bias[1];
        v0.z = acc[i][2] + bias[2]; v0.w = acc[i][3] + bias[3];
        v1.x = acc[i][4] + bias[4]; v1.y = acc[i][5] + bias[5];
        v1.z = acc[i][6] + bias[6]; v1.w = acc[i][7] + bias[7];
        *(float4*)&g_pre[row]     = v0;
        *(float4*)&g_pre[row + 4] = v1;
    }
}

// ---------------------------------------------------------------------------
// Kernel 2: persistent BiLSTM recurrence. 128 blocks x 256 threads (NEW).
// Block = (dir, kgroup of 24 h-cols, bgroup of 16 batches); 1 block/SM.
// Thread = (rg: 3 gate-rows, bq: 4 batches via float4, kh: k-parity class).
// kh pair (adjacent lanes) reduces via shfl; even lane writes gate_s.
// k-parity split keeps h_s bank halves disjoint (16k mod 32) -> conflict-free.
// ---------------------------------------------------------------------------
__device__ __forceinline__ float sigf(float x) { return 1.f / (1.f + expf(-x)); }

#define REC_SMEM_FLOATS (96*388 + 384*16 + 96*17 + 384)

__global__ __launch_bounds__(256) void k_rec(
    const float* __restrict__ whf, const float* __restrict__ whb,
    const float* __restrict__ h0, const float* __restrict__ c0)
{
    extern __shared__ float sm[];
    float* w_s    = sm;              // [96][388]
    float* h_s    = sm + 96*388;     // [384][16]
    float* gate_s = h_s + 384*16;    // [96][17]
    float* c_s    = gate_s + 96*17;  // [24*16]

    const int bid = blockIdx.x;
    const int dir = bid >> 6;
    const int kg  = (bid >> 2) & 15;
    const int bg  = bid & 3;
    const int k0  = kg * 24, b0 = bg * 16;
    const int tid = threadIdx.x;
    const float* whh = dir ? whb : whf;

    for (int idx = tid; idx < 96*96; idx += 256) {
        int r = idx / 96, cq = (idx - r*96) * 4;
        int gate = r / 24, kk = r - gate*24;
        float4 v = *(const float4*)(whh + (size_t)(gate*384 + k0 + kk) * 384 + cq);
        *(float4*)&w_s[r*388 + cq] = v;
    }
    for (int idx = tid; idx < 384; idx += 256) {
        int kk = idx >> 4, b = idx & 15;
        c_s[idx] = c0[((size_t)dir*64 + b0 + b) * 384 + k0 + kk];
    }
    __syncthreads();

    const int rg = tid >> 3;          // 0..31 -> rows 3rg..3rg+2
    const int bq = (tid >> 1) & 3;    // batches 4bq..4bq+3
    const int kh = tid & 1;           // k parity class
    const float* wr0 = w_s + (3*rg + 0) * 388;
    const float* wr1 = w_s + (3*rg + 1) * 388;
    const float* wr2 = w_s + (3*rg + 2) * 388;
    int grow[3];
#pragma unroll
    for (int i = 0; i < 3; i++) {
        int r = 3*rg + i;
        grow[i] = dir*1536 + (r/24)*384 + k0 + (r - (r/24)*24);
    }
    volatile unsigned int* bar = &g_bar[dir*4 + bg];

    // x-projection (+biases) prefetch: only the kh==0 lane carries it
    float pre[3][4];
    {
        const int t0 = dir ? 511 : 0;
#pragma unroll
        for (int i = 0; i < 3; i++)
#pragma unroll
            for (int j = 0; j < 4; j++)
                pre[i][j] = (kh == 0)
                    ? g_pre[((size_t)t0*64 + b0 + 4*bq + j) * 3072 + grow[i]]
                    : 0.f;
    }

    for (int s = 0; s < 512; s++) {
        const int t = dir ? (511 - s) : s;

        if (s == 0) {
            for (int idx = tid; idx < 384*16; idx += 256) {
                int k = idx >> 4, b = idx & 15;
                h_s[idx] = h0[((size_t)dir*64 + b0 + b) * 384 + k];
            }
        } else {
            const int tp = dir ? (t + 1) : (t - 1);
            const float* hp = &g_h[dir][tp][0][b0];
            for (int idx = tid; idx < 384*4; idx += 256) {
                int k = idx >> 2, q = idx & 3;
                float4 v = *(const float4*)(hp + (size_t)k*64 + q*4);
                *(float4*)&h_s[k*16 + q*4] = v;
            }
        }
        __syncthreads();

        float a00 = pre[0][0], a01 = pre[0][1], a02 = pre[0][2], a03 = pre[0][3];
        float a10 = pre[1][0], a11 = pre[1][1], a12 = pre[1][2], a13 = pre[1][3];
        float a20 = pre[2][0], a21 = pre[2][1], a22 = pre[2][2], a23 = pre[2][3];

#pragma unroll 4
        for (int q = 0; q < 384; q += 2) {
            const int k = q + kh;                       // this thread's parity
            float4 h4 = *(const float4*)&h_s[k*16 + bq*4];
            float w0 = wr0[k], w1 = wr1[k], w2 = wr2[k];
            a00 = fmaf(w0, h4.x, a00); a01 = fmaf(w0, h4.y, a01);
            a02 = fmaf(w0, h4.z, a02); a03 = fmaf(w0, h4.w, a03);
            a10 = fmaf(w1, h4.x, a10); a11 = fmaf(w1, h4.y, a11);
            a12 = fmaf(w1, h4.z, a12); a13 = fmaf(w1, h4.w, a13);
            a20 = fmaf(w2, h4.x, a20); a21 = fmaf(w2, h4.y, a21);
            a22 = fmaf(w2, h4.z, a22); a23 = fmaf(w2, h4.w, a23);
        }

        // combine parity partials: even lane += odd lane
        a00 += __shfl_down_sync(0xffffffffu, a00, 1);
        a01 += __shfl_down_sync(0xffffffffu, a01, 1);
        a02 += __shfl_down_sync(0xffffffffu, a02, 1);
        a03 += __shfl_down_sync(0xffffffffu, a03, 1);
        a10 += __shfl_down_sync(0xffffffffu, a10, 1);
        a11 += __shfl_down_sync(0xffffffffu, a11, 1);
        a12 += __shfl_down_sync(0xffffffffu, a12, 1);
        a13 += __shfl_down_sync(0xffffffffu, a13, 1);
        a20 += __shfl_down_sync(0xffffffffu, a20, 1);
        a21 += __shfl_down_sync(0xffffffffu, a21, 1);
        a22 += __shfl_down_sync(0xffffffffu, a22, 1);
        a23 += __shfl_down_sync(0xffffffffu, a23, 1);

        if (kh == 0) {
            float* gp0 = &gate_s[(3*rg + 0)*17 + 4*bq];
            float* gp1 = &gate_s[(3*rg + 1)*17 + 4*bq];
            float* gp2 = &gate_s[(3*rg + 2)*17 + 4*bq];
            gp0[0] = a00; gp0[1] = a01; gp0[2] = a02; gp0[3] = a03;
            gp1[0] = a10; gp1[1] = a11; gp1[2] = a12; gp1[3] = a13;
            gp2[0] = a20; gp2[1] = a21; gp2[2] = a22; gp2[3] = a23;
        }
        __syncthreads();

        // elementwise LSTM cell update (gate order i,f,g,o)
        for (int idx = tid; idx < 384; idx += 256) {
            int kk = idx >> 4, b = idx & 15;
            float gi = gate_s[(kk     )*17 + b];
            float gf = gate_s[(kk + 24)*17 + b];
            float gg = gate_s[(kk + 48)*17 + b];
            float go = gate_s[(kk + 72)*17 + b];
            float c = sigf(gf) * c_s[idx] + sigf(gi) * tanhf(gg);
            c_s[idx] = c;
            g_h[dir][t][k0 + kk][b0 + b] = sigf(go) * tanhf(c);
        }
        __threadfence();
        __syncthreads();

        if (tid == 0) atomicAdd((unsigned int*)&g_bar[dir*4 + bg], 1u);

        // hide next step's g_pre latency behind the barrier (kh==0 lanes)
        if (s + 1 < 512 && kh == 0) {
            const int tn = dir ? (510 - s) : (s + 1);
#pragma unroll
            for (int i = 0; i < 3; i++)
#pragma unroll
                for (int j = 0; j < 4; j++)
                    pre[i][j] = g_pre[((size_t)tn*64 + b0 + 4*bq + j) * 3072 + grow[i]];
        }
        if (tid == 0) {
            const unsigned int target = 16u * (unsigned)(s + 1);
            while (*bar < target) { }
            __threadfence();
        }
        __syncthreads();
    }
}

// ---------------------------------------------------------------------------
// Kernel 3: emissions (unchanged)
// ---------------------------------------------------------------------------
__global__ __launch_bounds__(256) void k_fc(const float* __restrict__ fcw,
                                            const float* __restrict__ fcb)
{
    __shared__ float wsh[12*768];
    __shared__ float bsh[12];
    const int t = blockIdx.x;
    const int tid = threadIdx.x;
    for (int i = tid; i < 12*768; i += 256) wsh[i] = fcw[i];
    if (tid < 12) bsh[tid] = fcb[tid];
    __syncthreads();

    for (int o = tid; o < 768; o += 256) {
        int l = o >> 6, b = o & 63;
        const float* wl  = &wsh[l*768];
        const float* hp0 = &g_h[0][t][0][b];
        const float* hp1 = &g_h[1][t][0][b];
        float s0 = 0.f, s1 = 0.f, s2 = 0.f, s3 = 0.f;
#pragma unroll 4
        for (int k = 0; k < 384; k += 4) {
            s0 = fmaf(hp0[(size_t)(k+0)*64], wl[k+0], s0);
            s1 = fmaf(hp0[(size_t)(k+1)*64], wl[k+1], s1);
            s2 = fmaf(hp0[(size_t)(k+2)*64], wl[k+2], s2);
            s3 = fmaf(hp0[(size_t)(k+3)*64], wl[k+3], s3);
        }
#pragma unroll 4
        for (int k = 0; k < 384; k += 4) {
            s0 = fmaf(hp1[(size_t)(k+0)*64], wl[384+k+0], s0);
            s1 = fmaf(hp1[(size_t)(k+1)*64], wl[384+k+1], s1);
            s2 = fmaf(hp1[(size_t)(k+2)*64], wl[384+k+2], s2);
            s3 = fmaf(hp1[(size_t)(k+3)*64], wl[384+k+3], s3);
        }
        g_feat[t][b][l] = bsh[l] + ((s0 + s1) + (s2 + s3));
    }
}

// ---------------------------------------------------------------------------
// Kernel 4: Viterbi forward + backtrace (unchanged)
// ---------------------------------------------------------------------------
__global__ __launch_bounds__(768) void k_vit(const float* __restrict__ trans,
                                             const int* __restrict__ start_idx,
                                             float* __restrict__ out)
{
    __shared__ float fvbuf[2][64][12];
    __shared__ float tr[12][12];
    const int tid = threadIdx.x;
    const int b = tid / 12, l = tid - b*12;

    if (tid < 144) tr[tid / 12][tid % 12] = trans[tid];
    const int s0 = *start_idx;
    fvbuf[0][b][l] = (l == s0) ? 0.f : NEGV;
    __syncthreads();

    float ft_next = g_feat[1][b][l];
    for (int t = 1; t < 512; t++) {
        const float* fv = fvbuf[(t - 1) & 1][b];
        float ft = ft_next;
        if (t < 511) ft_next = g_feat[t + 1][b][l];
        float best = tr[l][0] + fv[0];
        int arg = 0;
#pragma unroll
        for (int p = 1; p < 12; p++) {
            float sc = tr[l][p] + fv[p];
            if (sc > best) { best = sc; arg = p; }
        }
        fvbuf[t & 1][b][l] = best + ft;
        g_ptr[t - 1][b][l] = (unsigned char)arg;
        __syncthreads();
    }

    if (tid < 64) {
        const int bb = tid;
        float best = fvbuf[1][bb][0];
        int last = 0;
#pragma unroll
        for (int p = 1; p < 12; p++)
            if (fvbuf[1][bb][p] > best) { best = fvbuf[1][bb][p]; last = p; }
        out[bb] = best;
        float* path = out + 64 + (size_t)bb * 512;
        int cur = last;
        path[511] = (float)cur;
        for (int t = 510; t >= 0; t--) {
            cur = g_ptr[t][bb][cur];
            path[t] = (float)cur;
        }
    }
}

// ---------------------------------------------------------------------------
extern "C" void kernel_launch(void* const* d_in, const int* in_sizes, int n_in,
                              void* d_out, int out_size)
{
    const float* hs   = (const float*)d_in[0];
    const float* h0   = (const float*)d_in[1];
    const float* c0   = (const float*)d_in[2];
    const float* wihf = (const float*)d_in[3];
    const float* whhf = (const float*)d_in[4];
    const float* bihf = (const float*)d_in[5];
    const float* bhhf = (const float*)d_in[6];
    const float* wihb = (const float*)d_in[7];
    const float* whhb = (const float*)d_in[8];
    const float* bihb = (const float*)d_in[9];
    const float* bhhb = (const float*)d_in[10];
    const float* fcw  = (const float*)d_in[11];
    const float* fcb  = (const float*)d_in[12];
    const float* trans= (const float*)d_in[13];
    const int*   stp  = (const int*)d_in[14];
    (void)in_sizes; (void)n_in; (void)out_size;

    const size_t rec_smem = (size_t)REC_SMEM_FLOATS * sizeof(float); // 181,632 B
    cudaFuncSetAttribute(k_rec, cudaFuncAttributeMaxDynamicSharedMemorySize,
                         (int)rec_smem);

    k_init<<<1, 32>>>();

    dim3 gg(24, 256);   // n-tiles fastest (A-row reuse in L2)
    k_gemm<<<gg, 256>>>(hs, wihf, wihb, bihf, bhhf, bihb, bhhb);

    k_rec<<<128, 256, rec_smem>>>(whhf, whhb, h0, c0);

    k_fc<<<512, 256>>>(fcw, fcb);

    k_vit<<<1, 768>>>(trans, stp, (float*)d_out);
}